// round 10
// baseline (speedup 1.0000x reference)
#include <cuda_runtime.h>
#include <cuda_fp16.h>
#include <cstdint>
#include <math.h>

#define N_NODES 131072
#define N_EDGES 2097152
#define N_GRAPHS 2048
#define IN_CH 12
#define HID 64
#define OUT_CH 4

// Scratch (device globals — no allocation allowed).
// Referenced ONLY inside device code (host-side use of __device__ symbols
// takes the host shadow address under ATS — the R2 bug).
__device__ int   g_degi[N_NODES];
__device__ float g_dinv[N_NODES];
__device__ int   g_rowstart[N_NODES];
__device__ int   g_cursor[N_NODES];
__device__ int   g_total;
__device__ int   g_csr_src[N_EDGES];                   // src only (norm factored out)
__device__ uint4 g_Ah_raw[(size_t)N_NODES * HID / 8];  // h' = h*dinv as __half [N, 64]
__device__ uint4 g_Ah2_raw[(size_t)N_NODES * HID / 8]; // layer-2 h'
__device__ float g_pool[N_GRAPHS * HID];
__device__ float g_cnt[N_GRAPHS];

__device__ __forceinline__ void red_add_v2(float* addr, float2 v) {
    asm volatile("red.global.add.v2.f32 [%0], {%1,%2};"
                 :: "l"(addr), "f"(v.x), "f"(v.y) : "memory");
}

__device__ __forceinline__ unsigned int pack_half2(float a, float b) {
    __half2 h = __floats2half2_rn(a, b);
    return *(unsigned int*)&h;
}

// Warp-cooperative aggregation of one node: each lane owns 2 columns (2*lane).
// Indices pre-loaded per 32-edge chunk -> all feature row reads independent.
__device__ __forceinline__ float2 agg_node_warp(const __half* __restrict__ h,
                                                int node, int lane) {
    int beg = g_rowstart[node];
    int deg = g_degi[node];
    float2 acc;
    {   // self term h'[node]
        unsigned u = __ldg((const unsigned*)(h + (size_t)node * HID) + lane);
        float2 f = __half22float2(*(__half2*)&u);
        acc.x = f.x; acc.y = f.y;
    }
    for (int base = 0; base < deg; base += 32) {
        int n = deg - base; if (n > 32) n = 32;
        int idx = 0;
        if (lane < n) idx = __ldg(g_csr_src + beg + base + lane);
        #pragma unroll 4
        for (int k = 0; k < n; k++) {
            int s = __shfl_sync(0xFFFFFFFFu, idx, k);
            unsigned u = __ldg((const unsigned*)(h + (size_t)s * HID) + lane);
            float2 f = __half22float2(*(__half2*)&u);
            acc.x += f.x; acc.y += f.y;
        }
    }
    return acc;
}

// ---------------- zero deg / pool / cnt / total ----------------
__global__ void zero_kernel() {
    int i = blockIdx.x * blockDim.x + threadIdx.x;
    if (i < N_NODES) g_degi[i] = 0;
    if (i < N_GRAPHS * HID) g_pool[i] = 0.0f;
    if (i < N_GRAPHS) g_cnt[i] = 0.0f;
    if (i == 0) g_total = 0;
}

// ---------------- degree at dst (edges) + graph counts (nodes), one pass --------
__global__ void deg_cnt_kernel(const int* __restrict__ dst, const int* __restrict__ batch) {
    int t = blockIdx.x * blockDim.x + threadIdx.x;
    if (t < N_EDGES) atomicAdd(&g_degi[dst[t]], 1);
    if (t < N_NODES) {
        int g = batch[t];
        unsigned mask = __match_any_sync(__activemask(), g);
        int leader = __ffs(mask) - 1;
        if ((threadIdx.x & 31) == leader)
            atomicAdd(&g_cnt[g], (float)__popc(mask));
    }
}

// ---------------- dinv + warp-aggregated unordered scan -> rowstart/cursor ------
__global__ void scan_kernel() {
    int i = blockIdx.x * blockDim.x + threadIdx.x;
    int lane = threadIdx.x & 31;
    int d = g_degi[i];
    g_dinv[i] = rsqrtf((float)d + 1.0f);
    int v = d;
#pragma unroll
    for (int o = 1; o < 32; o <<= 1) {
        int t = __shfl_up_sync(0xFFFFFFFFu, v, o);
        if (lane >= o) v += t;
    }
    int total = __shfl_sync(0xFFFFFFFFu, v, 31);
    int base = 0;
    if (lane == 0) base = atomicAdd(&g_total, total);
    base = __shfl_sync(0xFFFFFFFFu, base, 0);
    int start = base + v - d;
    g_rowstart[i] = start;
    g_cursor[i] = start;
}

// ---------------- fill CSR (standalone, low regs, high occupancy) ----------------
__global__ void __launch_bounds__(256) fill_kernel(const int* __restrict__ src,
                                                   const int* __restrict__ dst) {
    int e = blockIdx.x * blockDim.x + threadIdx.x;
    int s = src[e];
    int d = dst[e];
    int pos = atomicAdd(&g_cursor[d], 1);
    g_csr_src[pos] = s;
}

// ---------------- GEMM1: g_Ah = half((x @ W1) * dinv[row])  ----------------
__global__ void gemm1_kernel(const float* __restrict__ x, const float* __restrict__ W1) {
    __shared__ float Ws[IN_CH * HID];   // 768
    __shared__ float Xs[64 * IN_CH];    // 768
    int tid = threadIdx.x;
    for (int i = tid; i < IN_CH * HID; i += 256) Ws[i] = W1[i];
    const float* xb = x + (size_t)blockIdx.x * 64 * IN_CH;
    for (int i = tid; i < 64 * IN_CH; i += 256) Xs[i] = xb[i];
    __syncthreads();
    int row = tid >> 2;
    int cb  = (tid & 3) << 4;
    int grow = blockIdx.x * 64 + row;
    float acc[16];
#pragma unroll
    for (int j = 0; j < 16; j++) acc[j] = 0.0f;
#pragma unroll
    for (int k = 0; k < IN_CH; k++) {
        float xv = Xs[row * IN_CH + k];
#pragma unroll
        for (int j = 0; j < 16; j++) acc[j] = fmaf(xv, Ws[k * HID + cb + j], acc[j]);
    }
    float di = g_dinv[grow];
    __half* Ah = (__half*)g_Ah_raw;
    unsigned int p[8];
#pragma unroll
    for (int j = 0; j < 8; j++) p[j] = pack_half2(acc[2 * j] * di, acc[2 * j + 1] * di);
    uint4* o = (uint4*)(Ah + (size_t)grow * HID + cb);
    o[0] = make_uint4(p[0], p[1], p[2], p[3]);
    o[1] = make_uint4(p[4], p[5], p[6], p[7]);
}

// ---------------- fused: agg layer1 (to smem, ReLU) + GEMM2 -> g_Ah2 ------------
// Block = 256 threads / 64 nodes. Phase A: each warp aggregates 8 nodes
// (warp-per-node form), writes relu(dinv*sum + b1) rows to smem.
// Phase B: rows @ W2, scale by dinv, pack half -> g_Ah2.
__global__ void agg1_gemm2_kernel(const float* __restrict__ b1, const float* __restrict__ W2) {
    __shared__ float Ws[HID * HID];      // 16 KB
    __shared__ float rows[64 * 68];      // 17 KB
    const __half* h = (const __half*)g_Ah_raw;
    int tid = threadIdx.x;
    int rbase = blockIdx.x * 64;
    for (int i = tid; i < HID * HID; i += 256) Ws[i] = W2[i];

    int wid = tid >> 5;
    int lane = tid & 31;
    float2 b = *(const float2*)(b1 + 2 * lane);
#pragma unroll
    for (int nn = 0; nn < 8; nn++) {
        int r = wid * 8 + nn;
        int node = rbase + r;
        float2 acc = agg_node_warp(h, node, lane);
        float di = g_dinv[node];
        float* o = rows + r * 68 + 2 * lane;
        o[0] = fmaxf(fmaf(acc.x, di, b.x), 0.f);
        o[1] = fmaxf(fmaf(acc.y, di, b.y), 0.f);
    }
    __syncthreads();

    // ---- Phase B: GEMM2 ----
    int r = tid >> 2;
    int cb = (tid & 3) << 4;
    float acc[16];
#pragma unroll
    for (int j = 0; j < 16; j++) acc[j] = 0.0f;
#pragma unroll
    for (int k = 0; k < HID; k++) {
        float xv = rows[r * 68 + k];
        const float4* w = (const float4*)&Ws[k * HID + cb];
#pragma unroll
        for (int q = 0; q < 4; q++) {
            float4 wv = w[q];
            acc[4 * q + 0] = fmaf(xv, wv.x, acc[4 * q + 0]);
            acc[4 * q + 1] = fmaf(xv, wv.y, acc[4 * q + 1]);
            acc[4 * q + 2] = fmaf(xv, wv.z, acc[4 * q + 2]);
            acc[4 * q + 3] = fmaf(xv, wv.w, acc[4 * q + 3]);
        }
    }
    float di = g_dinv[rbase + r];
    __half* Ah2 = (__half*)g_Ah2_raw;
    unsigned int p[8];
#pragma unroll
    for (int j = 0; j < 8; j++) p[j] = pack_half2(acc[2 * j] * di, acc[2 * j + 1] * di);
    uint4* o = (uint4*)(Ah2 + (size_t)(rbase + r) * HID + cb);
    o[0] = make_uint4(p[0], p[1], p[2], p[3]);
    o[1] = make_uint4(p[4], p[5], p[6], p[7]);
}

// ---------------- agg layer2: warp per node + fused ReLU + pool red --------------
__global__ void agg2_kernel(const float* __restrict__ b2, const int* __restrict__ batch) {
    const __half* h = (const __half*)g_Ah2_raw;
    int node = blockIdx.x * 8 + (threadIdx.x >> 5);
    int lane = threadIdx.x & 31;
    float2 acc = agg_node_warp(h, node, lane);
    float di = g_dinv[node];
    float2 b = *(const float2*)(b2 + 2 * lane);
    float2 r;
    r.x = fmaxf(fmaf(acc.x, di, b.x), 0.f);
    r.y = fmaxf(fmaf(acc.y, di, b.y), 0.f);
    int g = __ldg(batch + node);
    red_add_v2(g_pool + g * HID + 2 * lane, r);
}

// ---------------- head: out = sigmoid((pool/cnt) @ Wfc + bfc) ----------------
__global__ void head_kernel(const float* __restrict__ Wfc, const float* __restrict__ bfc,
                            float* __restrict__ out) {
    __shared__ float Wf[HID * OUT_CH];
    if (threadIdx.x < HID * OUT_CH) Wf[threadIdx.x] = Wfc[threadIdx.x];
    __syncthreads();
    int gt = blockIdx.x * blockDim.x + threadIdx.x;
    int g = gt >> 2;
    int o = gt & 3;
    float cnt = fmaxf(g_cnt[g], 1.0f);
    float inv = 1.0f / cnt;
    float s = 0.0f;
#pragma unroll
    for (int k = 0; k < HID; k++) s = fmaf(g_pool[g * HID + k], Wf[k * OUT_CH + o], s);
    s = fmaf(s, inv, bfc[o]);
    out[gt] = 1.0f / (1.0f + expf(-s));
}

extern "C" void kernel_launch(void* const* d_in, const int* in_sizes, int n_in,
                              void* d_out, int out_size) {
    const float* x   = (const float*)d_in[0];
    const int*   ei  = (const int*)d_in[1];
    const int*   bat = (const int*)d_in[2];
    const float* W1  = (const float*)d_in[3];
    const float* b1  = (const float*)d_in[4];
    const float* W2  = (const float*)d_in[5];
    const float* b2  = (const float*)d_in[6];
    const float* Wfc = (const float*)d_in[7];
    const float* bfc = (const float*)d_in[8];
    float* out = (float*)d_out;

    const int* src = ei;
    const int* dst = ei + N_EDGES;
    const int B = 256;

    zero_kernel<<<(N_NODES + B - 1) / B, B>>>();
    deg_cnt_kernel<<<N_EDGES / B, B>>>(dst, bat);
    scan_kernel<<<N_NODES / B, B>>>();
    fill_kernel<<<N_EDGES / B, B>>>(src, dst);
    gemm1_kernel<<<N_NODES / 64, B>>>(x, W1);
    agg1_gemm2_kernel<<<N_NODES / 64, B>>>(b1, W2);
    agg2_kernel<<<N_NODES / 8, B>>>(b2, bat);
    head_kernel<<<(N_GRAPHS * OUT_CH) / B, B>>>(Wfc, bfc, out);
}

// round 11
// speedup vs baseline: 1.0800x; 1.0800x over previous
#include <cuda_runtime.h>
#include <cuda_fp16.h>
#include <cstdint>
#include <math.h>

#define N_NODES 131072
#define N_EDGES 2097152
#define N_GRAPHS 2048
#define IN_CH 12
#define HID 64
#define OUT_CH 4

// Scratch (device globals — no allocation allowed).
// Referenced ONLY inside device code (host-side use of __device__ symbols
// takes the host shadow address under ATS — the R2 bug).
__device__ int   g_degi[N_NODES];
__device__ float g_dinv[N_NODES];
__device__ int   g_rowstart[N_NODES];
__device__ int   g_cursor[N_NODES];
__device__ int   g_total;
__device__ int   g_csr_src[N_EDGES];                   // src only (norm factored out)
__device__ uint4 g_Ah_raw[(size_t)N_NODES * HID / 8];  // h' = h*dinv as __half [N, 64]
__device__ uint4 g_Ah2_raw[(size_t)N_NODES * HID / 8]; // layer-2 h'
__device__ float g_pool[N_GRAPHS * HID];
__device__ float g_cnt[N_GRAPHS];

__device__ __forceinline__ void red_add_v4(float* addr, float4 v) {
    asm volatile("red.global.add.v4.f32 [%0], {%1,%2,%3,%4};"
                 :: "l"(addr), "f"(v.x), "f"(v.y), "f"(v.z), "f"(v.w)
                 : "memory");
}

__device__ __forceinline__ unsigned int pack_half2(float a, float b) {
    __half2 h = __floats2half2_rn(a, b);
    return *(unsigned int*)&h;
}

// accumulate one uint4 (8 halves) into acc[8]
__device__ __forceinline__ void acc_row8(float* acc, uint4 u) {
    float2 f0 = __half22float2(*(__half2*)&u.x);
    float2 f1 = __half22float2(*(__half2*)&u.y);
    float2 f2 = __half22float2(*(__half2*)&u.z);
    float2 f3 = __half22float2(*(__half2*)&u.w);
    acc[0] += f0.x; acc[1] += f0.y; acc[2] += f1.x; acc[3] += f1.y;
    acc[4] += f2.x; acc[5] += f2.y; acc[6] += f3.x; acc[7] += f3.y;
}

// 8-lane/edge aggregation core: warp handles one node, 4 edge groups in flight,
// CSR index software-pipelined (next index load overlaps current feature load).
// acc[8] per lane; result valid in grp==0 lanes after the shfl reduction.
__device__ __forceinline__ void agg_node8(float* acc, const __half* __restrict__ h,
                                          int node, int grp, int c) {
    int beg = g_rowstart[node];
    int end = beg + g_degi[node];
#pragma unroll
    for (int j = 0; j < 8; j++) acc[j] = 0.0f;
    if (grp == 0) {   // self term h'[node]
        uint4 u = __ldg((const uint4*)(h + (size_t)node * HID + c));
        acc_row8(acc, u);
    }
    int e = beg + grp;
    int s = (e < end) ? __ldg(g_csr_src + e) : 0;
    while (e < end) {
        int e2 = e + 4;
        int s2 = (e2 < end) ? __ldg(g_csr_src + e2) : 0;   // prefetch next index
        uint4 u = __ldg((const uint4*)(h + (size_t)s * HID + c));
        acc_row8(acc, u);
        s = s2;
        e = e2;
    }
#pragma unroll
    for (int j = 0; j < 8; j++) {
        acc[j] += __shfl_down_sync(0xFFFFFFFFu, acc[j], 16);
        acc[j] += __shfl_down_sync(0xFFFFFFFFu, acc[j], 8);
    }
}

// ---------------- zero deg / pool / cnt / total ----------------
__global__ void zero_kernel() {
    int i = blockIdx.x * blockDim.x + threadIdx.x;
    if (i < N_NODES) g_degi[i] = 0;
    if (i < N_GRAPHS * HID) g_pool[i] = 0.0f;
    if (i < N_GRAPHS) g_cnt[i] = 0.0f;
    if (i == 0) g_total = 0;
}

// ---------------- degree at dst (edges) + graph counts (nodes), one pass --------
__global__ void deg_cnt_kernel(const int* __restrict__ dst, const int* __restrict__ batch) {
    int t = blockIdx.x * blockDim.x + threadIdx.x;
    if (t < N_EDGES) atomicAdd(&g_degi[dst[t]], 1);
    if (t < N_NODES) {
        int g = batch[t];
        unsigned mask = __match_any_sync(__activemask(), g);
        int leader = __ffs(mask) - 1;
        if ((threadIdx.x & 31) == leader)
            atomicAdd(&g_cnt[g], (float)__popc(mask));
    }
}

// ---------------- dinv + warp-aggregated unordered scan -> rowstart/cursor ------
__global__ void scan_kernel() {
    int i = blockIdx.x * blockDim.x + threadIdx.x;
    int lane = threadIdx.x & 31;
    int d = g_degi[i];
    g_dinv[i] = rsqrtf((float)d + 1.0f);
    int v = d;
#pragma unroll
    for (int o = 1; o < 32; o <<= 1) {
        int t = __shfl_up_sync(0xFFFFFFFFu, v, o);
        if (lane >= o) v += t;
    }
    int total = __shfl_sync(0xFFFFFFFFu, v, 31);
    int base = 0;
    if (lane == 0) base = atomicAdd(&g_total, total);
    base = __shfl_sync(0xFFFFFFFFu, base, 0);
    int start = base + v - d;
    g_rowstart[i] = start;
    g_cursor[i] = start;
}

// ---------------- fill CSR (standalone, low regs, high occupancy) ----------------
__global__ void __launch_bounds__(256) fill_kernel(const int* __restrict__ src,
                                                   const int* __restrict__ dst) {
    int e = blockIdx.x * blockDim.x + threadIdx.x;
    int s = src[e];
    int d = dst[e];
    int pos = atomicAdd(&g_cursor[d], 1);
    g_csr_src[pos] = s;
}

// ---------------- GEMM1: g_Ah = half((x @ W1) * dinv[row])  ----------------
__global__ void gemm1_kernel(const float* __restrict__ x, const float* __restrict__ W1) {
    __shared__ float Ws[IN_CH * HID];   // 768
    __shared__ float Xs[64 * IN_CH];    // 768
    int tid = threadIdx.x;
    for (int i = tid; i < IN_CH * HID; i += 256) Ws[i] = W1[i];
    const float* xb = x + (size_t)blockIdx.x * 64 * IN_CH;
    for (int i = tid; i < 64 * IN_CH; i += 256) Xs[i] = xb[i];
    __syncthreads();
    int row = tid >> 2;
    int cb  = (tid & 3) << 4;
    int grow = blockIdx.x * 64 + row;
    float acc[16];
#pragma unroll
    for (int j = 0; j < 16; j++) acc[j] = 0.0f;
#pragma unroll
    for (int k = 0; k < IN_CH; k++) {
        float xv = Xs[row * IN_CH + k];
#pragma unroll
        for (int j = 0; j < 16; j++) acc[j] = fmaf(xv, Ws[k * HID + cb + j], acc[j]);
    }
    float di = g_dinv[grow];
    __half* Ah = (__half*)g_Ah_raw;
    unsigned int p[8];
#pragma unroll
    for (int j = 0; j < 8; j++) p[j] = pack_half2(acc[2 * j] * di, acc[2 * j + 1] * di);
    uint4* o = (uint4*)(Ah + (size_t)grow * HID + cb);
    o[0] = make_uint4(p[0], p[1], p[2], p[3]);
    o[1] = make_uint4(p[4], p[5], p[6], p[7]);
}

// ---------------- fused: agg layer1 (to smem, ReLU) + GEMM2 -> g_Ah2 ------------
// Block = 256 threads / 64 nodes. Phase A: each warp aggregates 8 nodes with the
// 8-lane/edge core, writing relu(dinv*sum + b1) rows to smem. Phase B: rows @ W2.
__global__ void agg1_gemm2_kernel(const float* __restrict__ b1, const float* __restrict__ W2) {
    __shared__ float Ws[HID * HID];      // 16 KB
    __shared__ float rows[64 * 68];      // 17 KB
    const __half* h = (const __half*)g_Ah_raw;
    int tid = threadIdx.x;
    int rbase = blockIdx.x * 64;
    for (int i = tid; i < HID * HID; i += 256) Ws[i] = W2[i];

    int wid = tid >> 5;
    int lane = tid & 31;
    int grp = lane >> 3;
    int sub = lane & 7;
    int c   = sub << 3;
#pragma unroll
    for (int nn = 0; nn < 8; nn++) {
        int r = wid * 8 + nn;
        int node = rbase + r;
        float acc[8];
        agg_node8(acc, h, node, grp, c);
        if (grp == 0) {
            float di = g_dinv[node];
            float4 bb0 = *(const float4*)(b1 + c);
            float4 bb1 = *(const float4*)(b1 + c + 4);
            float* o = rows + r * 68 + c;
            o[0] = fmaxf(fmaf(acc[0], di, bb0.x), 0.f);
            o[1] = fmaxf(fmaf(acc[1], di, bb0.y), 0.f);
            o[2] = fmaxf(fmaf(acc[2], di, bb0.z), 0.f);
            o[3] = fmaxf(fmaf(acc[3], di, bb0.w), 0.f);
            o[4] = fmaxf(fmaf(acc[4], di, bb1.x), 0.f);
            o[5] = fmaxf(fmaf(acc[5], di, bb1.y), 0.f);
            o[6] = fmaxf(fmaf(acc[6], di, bb1.z), 0.f);
            o[7] = fmaxf(fmaf(acc[7], di, bb1.w), 0.f);
        }
    }
    __syncthreads();

    // ---- Phase B: GEMM2 ----
    int r = tid >> 2;
    int cb = (tid & 3) << 4;
    float acc[16];
#pragma unroll
    for (int j = 0; j < 16; j++) acc[j] = 0.0f;
#pragma unroll
    for (int k = 0; k < HID; k++) {
        float xv = rows[r * 68 + k];
        const float4* w = (const float4*)&Ws[k * HID + cb];
#pragma unroll
        for (int q = 0; q < 4; q++) {
            float4 wv = w[q];
            acc[4 * q + 0] = fmaf(xv, wv.x, acc[4 * q + 0]);
            acc[4 * q + 1] = fmaf(xv, wv.y, acc[4 * q + 1]);
            acc[4 * q + 2] = fmaf(xv, wv.z, acc[4 * q + 2]);
            acc[4 * q + 3] = fmaf(xv, wv.w, acc[4 * q + 3]);
        }
    }
    float di = g_dinv[rbase + r];
    __half* Ah2 = (__half*)g_Ah2_raw;
    unsigned int p[8];
#pragma unroll
    for (int j = 0; j < 8; j++) p[j] = pack_half2(acc[2 * j] * di, acc[2 * j + 1] * di);
    uint4* o = (uint4*)(Ah2 + (size_t)(rbase + r) * HID + cb);
    o[0] = make_uint4(p[0], p[1], p[2], p[3]);
    o[1] = make_uint4(p[4], p[5], p[6], p[7]);
}

// ---------------- agg layer2: warp per node + fused ReLU + pool red --------------
__global__ void agg2_kernel(const float* __restrict__ b2, const int* __restrict__ batch) {
    const __half* h = (const __half*)g_Ah2_raw;
    int node = blockIdx.x * 8 + (threadIdx.x >> 5);
    int lane = threadIdx.x & 31;
    int grp = lane >> 3;
    int sub = lane & 7;
    int c   = sub << 3;
    float acc[8];
    agg_node8(acc, h, node, grp, c);
    if (grp == 0) {
        float di = g_dinv[node];
        float4 b0 = *(const float4*)(b2 + c);
        float4 b1 = *(const float4*)(b2 + c + 4);
        float4 r0, r1;
        r0.x = fmaxf(fmaf(acc[0], di, b0.x), 0.f);
        r0.y = fmaxf(fmaf(acc[1], di, b0.y), 0.f);
        r0.z = fmaxf(fmaf(acc[2], di, b0.z), 0.f);
        r0.w = fmaxf(fmaf(acc[3], di, b0.w), 0.f);
        r1.x = fmaxf(fmaf(acc[4], di, b1.x), 0.f);
        r1.y = fmaxf(fmaf(acc[5], di, b1.y), 0.f);
        r1.z = fmaxf(fmaf(acc[6], di, b1.z), 0.f);
        r1.w = fmaxf(fmaf(acc[7], di, b1.w), 0.f);
        int g = __ldg(batch + node);
        red_add_v4(g_pool + g * HID + c, r0);
        red_add_v4(g_pool + g * HID + c + 4, r1);
    }
}

// ---------------- head: out = sigmoid((pool/cnt) @ Wfc + bfc) ----------------
__global__ void head_kernel(const float* __restrict__ Wfc, const float* __restrict__ bfc,
                            float* __restrict__ out) {
    __shared__ float Wf[HID * OUT_CH];
    if (threadIdx.x < HID * OUT_CH) Wf[threadIdx.x] = Wfc[threadIdx.x];
    __syncthreads();
    int gt = blockIdx.x * blockDim.x + threadIdx.x;
    int g = gt >> 2;
    int o = gt & 3;
    float cnt = fmaxf(g_cnt[g], 1.0f);
    float inv = 1.0f / cnt;
    float s = 0.0f;
#pragma unroll
    for (int k = 0; k < HID; k++) s = fmaf(g_pool[g * HID + k], Wf[k * OUT_CH + o], s);
    s = fmaf(s, inv, bfc[o]);
    out[gt] = 1.0f / (1.0f + expf(-s));
}

extern "C" void kernel_launch(void* const* d_in, const int* in_sizes, int n_in,
                              void* d_out, int out_size) {
    const float* x   = (const float*)d_in[0];
    const int*   ei  = (const int*)d_in[1];
    const int*   bat = (const int*)d_in[2];
    const float* W1  = (const float*)d_in[3];
    const float* b1  = (const float*)d_in[4];
    const float* W2  = (const float*)d_in[5];
    const float* b2  = (const float*)d_in[6];
    const float* Wfc = (const float*)d_in[7];
    const float* bfc = (const float*)d_in[8];
    float* out = (float*)d_out;

    const int* src = ei;
    const int* dst = ei + N_EDGES;
    const int B = 256;

    zero_kernel<<<(N_NODES + B - 1) / B, B>>>();
    deg_cnt_kernel<<<N_EDGES / B, B>>>(dst, bat);
    scan_kernel<<<N_NODES / B, B>>>();
    fill_kernel<<<N_EDGES / B, B>>>(src, dst);
    gemm1_kernel<<<N_NODES / 64, B>>>(x, W1);
    agg1_gemm2_kernel<<<N_NODES / 64, B>>>(b1, W2);
    agg2_kernel<<<N_NODES / 8, B>>>(b2, bat);
    head_kernel<<<(N_GRAPHS * OUT_CH) / B, B>>>(Wfc, bfc, out);
}

// round 12
// speedup vs baseline: 1.0945x; 1.0135x over previous
#include <cuda_runtime.h>
#include <cuda_fp16.h>
#include <cstdint>
#include <math.h>

#define N_NODES 131072
#define N_EDGES 2097152
#define N_GRAPHS 2048
#define IN_CH 12
#define HID 64
#define OUT_CH 4

// Scratch (device globals — no allocation allowed).
// Referenced ONLY inside device code (host-side use of __device__ symbols
// takes the host shadow address under ATS — the R2 bug).
__device__ int   g_degi[N_NODES];
__device__ float g_dinv[N_NODES];
__device__ int   g_rowstart[N_NODES];
__device__ int   g_cursor[N_NODES];
__device__ int   g_total;
__device__ int   g_csr_src[N_EDGES];                   // src only (norm factored out)
__device__ uint4 g_Ah_raw[(size_t)N_NODES * HID / 8];  // h' = h*dinv as __half [N, 64]
__device__ uint4 g_Ah2_raw[(size_t)N_NODES * HID / 8]; // layer-2 h'
__device__ float g_pool[N_GRAPHS * HID];
__device__ float g_cnt[N_GRAPHS];

__device__ __forceinline__ void red_add_v4(float* addr, float4 v) {
    asm volatile("red.global.add.v4.f32 [%0], {%1,%2,%3,%4};"
                 :: "l"(addr), "f"(v.x), "f"(v.y), "f"(v.z), "f"(v.w)
                 : "memory");
}

__device__ __forceinline__ unsigned int pack_half2(float a, float b) {
    __half2 h = __floats2half2_rn(a, b);
    return *(unsigned int*)&h;
}

// accumulate one uint4 (8 halves) into acc[8]
__device__ __forceinline__ void acc_row8(float* acc, uint4 u) {
    float2 f0 = __half22float2(*(__half2*)&u.x);
    float2 f1 = __half22float2(*(__half2*)&u.y);
    float2 f2 = __half22float2(*(__half2*)&u.z);
    float2 f3 = __half22float2(*(__half2*)&u.w);
    acc[0] += f0.x; acc[1] += f0.y; acc[2] += f1.x; acc[3] += f1.y;
    acc[4] += f2.x; acc[5] += f2.y; acc[6] += f3.x; acc[7] += f3.y;
}

// Dual-node 8-lane/edge aggregation: one warp aggregates TWO nodes concurrently.
// Two independent edge streams -> overlapped startup chains + 2 feature loads
// in flight per iteration. Results valid in grp==0 lanes after reduction.
__device__ __forceinline__ void agg_node8_dual(float* accA, float* accB,
                                               const __half* __restrict__ h,
                                               int nodeA, int nodeB, int grp, int c) {
    int begA = g_rowstart[nodeA];
    int endA = begA + g_degi[nodeA];
    int begB = g_rowstart[nodeB];
    int endB = begB + g_degi[nodeB];
#pragma unroll
    for (int j = 0; j < 8; j++) { accA[j] = 0.0f; accB[j] = 0.0f; }
    if (grp == 0) {   // self terms (independent loads)
        uint4 uA = __ldg((const uint4*)(h + (size_t)nodeA * HID + c));
        uint4 uB = __ldg((const uint4*)(h + (size_t)nodeB * HID + c));
        acc_row8(accA, uA);
        acc_row8(accB, uB);
    }
    int eA = begA + grp, eB = begB + grp;
    int sA = (eA < endA) ? __ldg(g_csr_src + eA) : 0;
    int sB = (eB < endB) ? __ldg(g_csr_src + eB) : 0;
    while (eA < endA || eB < endB) {
        // prefetch next indices (overlap with feature loads below)
        int sA2 = (eA + 4 < endA) ? __ldg(g_csr_src + eA + 4) : 0;
        int sB2 = (eB + 4 < endB) ? __ldg(g_csr_src + eB + 4) : 0;
        if (eA < endA) {
            uint4 u = __ldg((const uint4*)(h + (size_t)sA * HID + c));
            acc_row8(accA, u);
        }
        if (eB < endB) {
            uint4 u = __ldg((const uint4*)(h + (size_t)sB * HID + c));
            acc_row8(accB, u);
        }
        sA = sA2; sB = sB2;
        eA += 4;  eB += 4;
    }
#pragma unroll
    for (int j = 0; j < 8; j++) {
        accA[j] += __shfl_down_sync(0xFFFFFFFFu, accA[j], 16);
        accA[j] += __shfl_down_sync(0xFFFFFFFFu, accA[j], 8);
        accB[j] += __shfl_down_sync(0xFFFFFFFFu, accB[j], 16);
        accB[j] += __shfl_down_sync(0xFFFFFFFFu, accB[j], 8);
    }
}

// ---------------- zero deg / pool / cnt / total ----------------
__global__ void zero_kernel() {
    int i = blockIdx.x * blockDim.x + threadIdx.x;
    if (i < N_NODES) g_degi[i] = 0;
    if (i < N_GRAPHS * HID) g_pool[i] = 0.0f;
    if (i < N_GRAPHS) g_cnt[i] = 0.0f;
    if (i == 0) g_total = 0;
}

// ---------------- degree at dst (edges) + graph counts (nodes), one pass --------
__global__ void deg_cnt_kernel(const int* __restrict__ dst, const int* __restrict__ batch) {
    int t = blockIdx.x * blockDim.x + threadIdx.x;
    if (t < N_EDGES) atomicAdd(&g_degi[dst[t]], 1);
    if (t < N_NODES) {
        int g = batch[t];
        unsigned mask = __match_any_sync(__activemask(), g);
        int leader = __ffs(mask) - 1;
        if ((threadIdx.x & 31) == leader)
            atomicAdd(&g_cnt[g], (float)__popc(mask));
    }
}

// ---------------- dinv + warp-aggregated unordered scan -> rowstart/cursor ------
__global__ void scan_kernel() {
    int i = blockIdx.x * blockDim.x + threadIdx.x;
    int lane = threadIdx.x & 31;
    int d = g_degi[i];
    g_dinv[i] = rsqrtf((float)d + 1.0f);
    int v = d;
#pragma unroll
    for (int o = 1; o < 32; o <<= 1) {
        int t = __shfl_up_sync(0xFFFFFFFFu, v, o);
        if (lane >= o) v += t;
    }
    int total = __shfl_sync(0xFFFFFFFFu, v, 31);
    int base = 0;
    if (lane == 0) base = atomicAdd(&g_total, total);
    base = __shfl_sync(0xFFFFFFFFu, base, 0);
    int start = base + v - d;
    g_rowstart[i] = start;
    g_cursor[i] = start;
}

// ---------------- fill CSR (standalone, low regs, high occupancy) ----------------
__global__ void __launch_bounds__(256) fill_kernel(const int* __restrict__ src,
                                                   const int* __restrict__ dst) {
    int e = blockIdx.x * blockDim.x + threadIdx.x;
    int s = src[e];
    int d = dst[e];
    int pos = atomicAdd(&g_cursor[d], 1);
    g_csr_src[pos] = s;
}

// ---------------- GEMM1: g_Ah = half((x @ W1) * dinv[row])  ----------------
__global__ void gemm1_kernel(const float* __restrict__ x, const float* __restrict__ W1) {
    __shared__ float Ws[IN_CH * HID];   // 768
    __shared__ float Xs[64 * IN_CH];    // 768
    int tid = threadIdx.x;
    for (int i = tid; i < IN_CH * HID; i += 256) Ws[i] = W1[i];
    const float* xb = x + (size_t)blockIdx.x * 64 * IN_CH;
    for (int i = tid; i < 64 * IN_CH; i += 256) Xs[i] = xb[i];
    __syncthreads();
    int row = tid >> 2;
    int cb  = (tid & 3) << 4;
    int grow = blockIdx.x * 64 + row;
    float acc[16];
#pragma unroll
    for (int j = 0; j < 16; j++) acc[j] = 0.0f;
#pragma unroll
    for (int k = 0; k < IN_CH; k++) {
        float xv = Xs[row * IN_CH + k];
#pragma unroll
        for (int j = 0; j < 16; j++) acc[j] = fmaf(xv, Ws[k * HID + cb + j], acc[j]);
    }
    float di = g_dinv[grow];
    __half* Ah = (__half*)g_Ah_raw;
    unsigned int p[8];
#pragma unroll
    for (int j = 0; j < 8; j++) p[j] = pack_half2(acc[2 * j] * di, acc[2 * j + 1] * di);
    uint4* o = (uint4*)(Ah + (size_t)grow * HID + cb);
    o[0] = make_uint4(p[0], p[1], p[2], p[3]);
    o[1] = make_uint4(p[4], p[5], p[6], p[7]);
}

// epilogue: rows[r] = relu(dinv*acc + bias) into smem (grp==0 lanes)
__device__ __forceinline__ void store_row_smem(float* rows, int r, int c,
                                               const float* acc, float di,
                                               const float* __restrict__ bias) {
    float4 bb0 = *(const float4*)(bias + c);
    float4 bb1 = *(const float4*)(bias + c + 4);
    float* o = rows + r * 68 + c;
    o[0] = fmaxf(fmaf(acc[0], di, bb0.x), 0.f);
    o[1] = fmaxf(fmaf(acc[1], di, bb0.y), 0.f);
    o[2] = fmaxf(fmaf(acc[2], di, bb0.z), 0.f);
    o[3] = fmaxf(fmaf(acc[3], di, bb0.w), 0.f);
    o[4] = fmaxf(fmaf(acc[4], di, bb1.x), 0.f);
    o[5] = fmaxf(fmaf(acc[5], di, bb1.y), 0.f);
    o[6] = fmaxf(fmaf(acc[6], di, bb1.z), 0.f);
    o[7] = fmaxf(fmaf(acc[7], di, bb1.w), 0.f);
}

// ---------------- fused: agg layer1 (to smem, ReLU) + GEMM2 -> g_Ah2 ------------
// Block = 256 threads / 64 nodes. Phase A: each warp aggregates 8 nodes as
// 4 dual-node calls. Phase B: rows @ W2, scale by dinv, pack half -> g_Ah2.
__global__ void agg1_gemm2_kernel(const float* __restrict__ b1, const float* __restrict__ W2) {
    __shared__ float Ws[HID * HID];      // 16 KB
    __shared__ float rows[64 * 68];      // 17 KB
    const __half* h = (const __half*)g_Ah_raw;
    int tid = threadIdx.x;
    int rbase = blockIdx.x * 64;
    for (int i = tid; i < HID * HID; i += 256) Ws[i] = W2[i];

    int wid = tid >> 5;
    int lane = tid & 31;
    int grp = lane >> 3;
    int sub = lane & 7;
    int c   = sub << 3;
#pragma unroll
    for (int nn = 0; nn < 4; nn++) {
        int rA = wid * 8 + 2 * nn;
        int rB = rA + 1;
        int nodeA = rbase + rA;
        int nodeB = rbase + rB;
        float accA[8], accB[8];
        agg_node8_dual(accA, accB, h, nodeA, nodeB, grp, c);
        if (grp == 0) {
            store_row_smem(rows, rA, c, accA, g_dinv[nodeA], b1);
            store_row_smem(rows, rB, c, accB, g_dinv[nodeB], b1);
        }
    }
    __syncthreads();

    // ---- Phase B: GEMM2 ----
    int r = tid >> 2;
    int cb = (tid & 3) << 4;
    float acc[16];
#pragma unroll
    for (int j = 0; j < 16; j++) acc[j] = 0.0f;
#pragma unroll
    for (int k = 0; k < HID; k++) {
        float xv = rows[r * 68 + k];
        const float4* w = (const float4*)&Ws[k * HID + cb];
#pragma unroll
        for (int q = 0; q < 4; q++) {
            float4 wv = w[q];
            acc[4 * q + 0] = fmaf(xv, wv.x, acc[4 * q + 0]);
            acc[4 * q + 1] = fmaf(xv, wv.y, acc[4 * q + 1]);
            acc[4 * q + 2] = fmaf(xv, wv.z, acc[4 * q + 2]);
            acc[4 * q + 3] = fmaf(xv, wv.w, acc[4 * q + 3]);
        }
    }
    float di = g_dinv[rbase + r];
    __half* Ah2 = (__half*)g_Ah2_raw;
    unsigned int p[8];
#pragma unroll
    for (int j = 0; j < 8; j++) p[j] = pack_half2(acc[2 * j] * di, acc[2 * j + 1] * di);
    uint4* o = (uint4*)(Ah2 + (size_t)(rbase + r) * HID + cb);
    o[0] = make_uint4(p[0], p[1], p[2], p[3]);
    o[1] = make_uint4(p[4], p[5], p[6], p[7]);
}

// epilogue: relu(dinv*acc + bias) -> red into pool (grp==0 lanes)
__device__ __forceinline__ void pool_node(const float* acc, float di,
                                          const float* __restrict__ bias,
                                          int node, int c, const int* __restrict__ batch) {
    float4 b0 = *(const float4*)(bias + c);
    float4 b1 = *(const float4*)(bias + c + 4);
    float4 r0, r1;
    r0.x = fmaxf(fmaf(acc[0], di, b0.x), 0.f);
    r0.y = fmaxf(fmaf(acc[1], di, b0.y), 0.f);
    r0.z = fmaxf(fmaf(acc[2], di, b0.z), 0.f);
    r0.w = fmaxf(fmaf(acc[3], di, b0.w), 0.f);
    r1.x = fmaxf(fmaf(acc[4], di, b1.x), 0.f);
    r1.y = fmaxf(fmaf(acc[5], di, b1.y), 0.f);
    r1.z = fmaxf(fmaf(acc[6], di, b1.z), 0.f);
    r1.w = fmaxf(fmaf(acc[7], di, b1.w), 0.f);
    int g = __ldg(batch + node);
    red_add_v4(g_pool + g * HID + c, r0);
    red_add_v4(g_pool + g * HID + c + 4, r1);
}

// ---------------- agg layer2: 2 nodes per warp + fused ReLU + pool red ----------
__global__ void agg2_kernel(const float* __restrict__ b2, const int* __restrict__ batch) {
    const __half* h = (const __half*)g_Ah2_raw;
    int wid = threadIdx.x >> 5;
    int nodeA = blockIdx.x * 16 + wid * 2;
    int nodeB = nodeA + 1;
    int lane = threadIdx.x & 31;
    int grp = lane >> 3;
    int sub = lane & 7;
    int c   = sub << 3;
    float accA[8], accB[8];
    agg_node8_dual(accA, accB, h, nodeA, nodeB, grp, c);
    if (grp == 0) {
        pool_node(accA, g_dinv[nodeA], b2, nodeA, c, batch);
        pool_node(accB, g_dinv[nodeB], b2, nodeB, c, batch);
    }
}

// ---------------- head: out = sigmoid((pool/cnt) @ Wfc + bfc) ----------------
__global__ void head_kernel(const float* __restrict__ Wfc, const float* __restrict__ bfc,
                            float* __restrict__ out) {
    __shared__ float Wf[HID * OUT_CH];
    if (threadIdx.x < HID * OUT_CH) Wf[threadIdx.x] = Wfc[threadIdx.x];
    __syncthreads();
    int gt = blockIdx.x * blockDim.x + threadIdx.x;
    int g = gt >> 2;
    int o = gt & 3;
    float cnt = fmaxf(g_cnt[g], 1.0f);
    float inv = 1.0f / cnt;
    float s = 0.0f;
#pragma unroll
    for (int k = 0; k < HID; k++) s = fmaf(g_pool[g * HID + k], Wf[k * OUT_CH + o], s);
    s = fmaf(s, inv, bfc[o]);
    out[gt] = 1.0f / (1.0f + expf(-s));
}

extern "C" void kernel_launch(void* const* d_in, const int* in_sizes, int n_in,
                              void* d_out, int out_size) {
    const float* x   = (const float*)d_in[0];
    const int*   ei  = (const int*)d_in[1];
    const int*   bat = (const int*)d_in[2];
    const float* W1  = (const float*)d_in[3];
    const float* b1  = (const float*)d_in[4];
    const float* W2  = (const float*)d_in[5];
    const float* b2  = (const float*)d_in[6];
    const float* Wfc = (const float*)d_in[7];
    const float* bfc = (const float*)d_in[8];
    float* out = (float*)d_out;

    const int* src = ei;
    const int* dst = ei + N_EDGES;
    const int B = 256;

    zero_kernel<<<(N_NODES + B - 1) / B, B>>>();
    deg_cnt_kernel<<<N_EDGES / B, B>>>(dst, bat);
    scan_kernel<<<N_NODES / B, B>>>();
    fill_kernel<<<N_EDGES / B, B>>>(src, dst);
    gemm1_kernel<<<N_NODES / 64, B>>>(x, W1);
    agg1_gemm2_kernel<<<N_NODES / 64, B>>>(b1, W2);
    agg2_kernel<<<N_NODES / 16, B>>>(b2, bat);
    head_kernel<<<(N_GRAPHS * OUT_CH) / B, B>>>(Wfc, bfc, out);
}